// round 1
// baseline (speedup 1.0000x reference)
#include <cuda_runtime.h>

// Problem shapes (fixed by the dataset):
//   x:                  [N_PTS,  N_NODES] float32
//   learned_edge_states:[N_CMP,  N_NODES] int32 (values 0..2; 0 == EDG_NULL)
// Output: concat( new_comp_code [N_PTS, N_CMP] f32,
//                 premerge_idx  [N_PTS, N_CMP] f32 )
#define N_PTS   256
#define N_NODES 1024
#define N_CMP   1024
#define MASK_WORDS (N_NODES / 32)

// Static device scratch (allocation-free rule): 128 KB of mask bits.
__device__ unsigned d_maskbits[N_CMP * MASK_WORDS];

// ---------------------------------------------------------------------------
// Kernel 1: pack learned_edge_states != 0 into bit rows (one 128B line per
// component). Fully coalesced: each warp reads 32 consecutive int32 and
// ballots them into one word.
// ---------------------------------------------------------------------------
__global__ void pack_mask_kernel(const int* __restrict__ edges) {
    unsigned g = blockIdx.x * blockDim.x + threadIdx.x;   // 0 .. N_CMP*N_NODES-1
    int v = edges[g];
    unsigned ballot = __ballot_sync(0xFFFFFFFFu, v != 0);
    if ((g & 31u) == 0u) {
        d_maskbits[g >> 5] = ballot;
    }
}

// ---------------------------------------------------------------------------
// Kernel 2 (fused): one block per point p.
//  Phase A: bitonic-sort the 1024 nodes of this point by |x| descending,
//           index ascending on exact ties (matches jnp.argmax first-occurrence).
//           Key: (float_bits(|x|) << 10) | (1023 - n), sorted descending as u64.
//           Positive-float bit patterns are order-isomorphic to the values.
//  Phase B: thread t == component c walks the sorted list; the FIRST node whose
//           mask bit is set is the masked max AND its argmax. Expected 1.5
//           probes per cell (mask density 2/3); scanning all 1024 guarantees
//           correctness (and empty rows fall through to 0,0).
// ---------------------------------------------------------------------------
__global__ __launch_bounds__(N_NODES)
void sort_probe_kernel(const float* __restrict__ x,
                       float* __restrict__ out_code,
                       float* __restrict__ out_idx) {
    __shared__ unsigned long long s[N_NODES];   // 8 KB

    const int p = blockIdx.x;
    const int t = threadIdx.x;

    // Build key
    float xv = x[p * N_NODES + t];
    unsigned vb = __float_as_uint(fabsf(xv));
    s[t] = (((unsigned long long)vb) << 10) | (unsigned)((N_NODES - 1) - t);
    __syncthreads();

    // Bitonic sort, descending (dir==true block keeps larger element first)
    #pragma unroll 1
    for (unsigned k = 2; k <= N_NODES; k <<= 1) {
        #pragma unroll 1
        for (unsigned j = k >> 1; j > 0; j >>= 1) {
            unsigned ixj = (unsigned)t ^ j;
            if (ixj > (unsigned)t) {
                unsigned long long a = s[t];
                unsigned long long b = s[ixj];
                bool dir = ((t & k) == 0);
                if (dir ? (a < b) : (a > b)) {
                    s[t]   = b;
                    s[ixj] = a;
                }
            }
            __syncthreads();
        }
    }

    // Phase B: probe. Thread t owns component c = t.
    const unsigned* mrow = d_maskbits + t * MASK_WORDS;  // 128B row, 1 line
    float code = 0.0f;
    float fidx = 0.0f;
    #pragma unroll 1
    for (int kk = 0; kk < N_NODES; ++kk) {
        unsigned long long key = s[kk];
        int n = (N_NODES - 1) - (int)(key & (unsigned)(N_NODES - 1));
        unsigned w = mrow[n >> 5];
        if ((w >> (n & 31)) & 1u) {
            code = __uint_as_float((unsigned)(key >> 10));
            fidx = (float)n;
            break;
        }
    }

    out_code[p * N_CMP + t] = code;
    out_idx [p * N_CMP + t] = fidx;
}

// ---------------------------------------------------------------------------
extern "C" void kernel_launch(void* const* d_in, const int* in_sizes, int n_in,
                              void* d_out, int out_size) {
    const float* x     = (const float*)d_in[0];
    const int*   edges = (const int*)  d_in[1];
    float*       out   = (float*)d_out;

    // 1) pack mask bits (1024 blocks x 1024 threads covers N_CMP*N_NODES)
    pack_mask_kernel<<<(N_CMP * N_NODES) / 1024, 1024>>>(edges);

    // 2) fused per-point sort + probe
    sort_probe_kernel<<<N_PTS, N_NODES>>>(x, out, out + (size_t)N_PTS * N_CMP);
}

// round 2
// speedup vs baseline: 1.6325x; 1.6325x over previous
#include <cuda_runtime.h>

// Shapes fixed by the dataset:
//   x:                   [N_PTS,  N_NODES] float32
//   learned_edge_states: [N_CMP,  N_NODES] int32 (0 == EDG_NULL)
// Output: concat( new_comp_code [N_PTS,N_CMP] f32, premerge_idx [N_PTS,N_CMP] f32 )
#define N_PTS   256
#define N_NODES 1024
#define N_CMP   1024

// Transposed mask bits: maskT[n*32 + cg] holds bit c&31 for components cg*32+bit.
// 128 KB static scratch (allocation-free rule) — L2-resident.
__device__ unsigned d_maskT[N_NODES * (N_CMP / 32)];

// ---------------------------------------------------------------------------
// Kernel 1: pack + transpose the edge-state mask.
// Block bx handles the 32x32 tile (components cg*32.., nodes nch*32..).
// Coalesced 128B reads per warp; ballot packs bits over n; smem transposes to
// bits over c.
// ---------------------------------------------------------------------------
__global__ __launch_bounds__(1024)
void pack_transpose_kernel(const int* __restrict__ edges) {
    __shared__ unsigned W[32];
    const unsigned bx   = blockIdx.x;
    const unsigned cg   = bx & 31;          // component group (32 comps)
    const unsigned nch  = bx >> 5;          // node chunk (32 nodes)
    const unsigned w    = threadIdx.x >> 5;
    const unsigned lane = threadIdx.x & 31;

    int v = edges[(cg * 32 + w) * N_NODES + nch * 32 + lane];
    unsigned b = __ballot_sync(0xFFFFFFFFu, v != 0);   // bits indexed by n-offset
    if (lane == 0) W[w] = b;
    __syncthreads();

    if (threadIdx.x < 32) {                 // transpose 32x32 bit tile
        unsigned T = 0;
        #pragma unroll
        for (int c = 0; c < 32; ++c) T |= ((W[c] >> threadIdx.x) & 1u) << c;
        d_maskT[(nch * 32 + threadIdx.x) * 32 + cg] = T;
    }
}

// ---------------------------------------------------------------------------
// Kernel 2: per-point exact top-32 selection (warp-register bitonics) + probe.
// Key: (bits(|x|) << 10) | (1023 - n)  -> max key == max value, min index.
// ---------------------------------------------------------------------------
__device__ __forceinline__ unsigned long long u64max(unsigned long long a,
                                                     unsigned long long b) {
    return a > b ? a : b;
}

__global__ __launch_bounds__(1024)
void topk_probe_kernel(const float* __restrict__ x,
                       float* __restrict__ out_code,
                       float* __restrict__ out_idx) {
    __shared__ unsigned long long s_keys[N_NODES];  // by node (fallback)
    __shared__ unsigned long long s_a[N_NODES];     // merge ping
    __shared__ unsigned long long s_b[N_NODES];     // merge pong

    const int p    = blockIdx.x;
    const int t    = threadIdx.x;
    const int w    = t >> 5;
    const int lane = t & 31;

    // ---- build key ----
    float xv = x[p * N_NODES + t];
    unsigned vb = __float_as_uint(fabsf(xv));
    unsigned long long key =
        (((unsigned long long)vb) << 10) | (unsigned)((N_NODES - 1) - t);
    s_keys[t] = key;

    // ---- warp-register bitonic sort (ascending), 15 stages, no barriers ----
    #pragma unroll
    for (int k = 2; k <= 32; k <<= 1) {
        #pragma unroll
        for (int j = k >> 1; j > 0; j >>= 1) {
            unsigned long long other = __shfl_xor_sync(0xFFFFFFFFu, key, j);
            bool dirUp = ((lane & k) == 0);
            bool lower = ((lane & j) == 0);
            unsigned long long mn = key < other ? key : other;
            unsigned long long mx = key < other ? other : key;
            key = (dirUp == lower) ? mn : mx;
        }
    }
    // write run descending
    s_a[w * 32 + (31 - lane)] = key;
    __syncthreads();

    // ---- 5 rounds of bitonic top-32 merge: 32 runs -> 1 run ----
    unsigned long long* bin  = s_a;
    unsigned long long* bout = s_b;
    #pragma unroll
    for (int r = 0; r < 5; ++r) {
        int nm = 16 >> r;                   // merges this round
        if (w < nm) {
            unsigned long long a = bin[(2 * w) * 32 + lane];
            unsigned long long b = bin[(2 * w + 1) * 32 + (31 - lane)];
            unsigned long long m = u64max(a, b);   // bitonic, contains top-32
            #pragma unroll
            for (int j = 16; j > 0; j >>= 1) {     // bitonic merge, descending
                unsigned long long other = __shfl_xor_sync(0xFFFFFFFFu, m, j);
                bool lower = ((lane & j) == 0);
                unsigned long long mn = m < other ? m : other;
                unsigned long long mx = m < other ? other : m;
                m = lower ? mx : mn;
            }
            bout[w * 32 + lane] = m;
        }
        __syncthreads();
        unsigned long long* tmp = bin; bin = bout; bout = tmp;
    }
    const unsigned long long* s_top = bin;  // top-32 sorted descending

    // ---- probe: thread t == component t; first masked node in top-32 ----
    const unsigned cg  = (unsigned)t >> 5;
    const unsigned bit = (unsigned)t & 31;
    float code = 0.0f, fidx = 0.0f;
    bool found = false;
    #pragma unroll 4
    for (int kk = 0; kk < 32; ++kk) {
        unsigned long long k2 = s_top[kk];                 // smem broadcast
        int n = (N_NODES - 1) - (int)(k2 & 1023ull);
        unsigned wrd = d_maskT[(unsigned)n * 32 + cg];     // uniform per warp
        if ((wrd >> bit) & 1u) {
            code = __uint_as_float((unsigned)(k2 >> 10));
            fidx = (float)n;
            found = true;
            break;
        }
    }

    // ---- exact fallback (P ~ 5e-16 per cell; also covers empty rows) ----
    if (!found) {
        unsigned long long best = 0; bool has = false;
        for (int n = 0; n < N_NODES; ++n) {
            unsigned wrd = d_maskT[(unsigned)n * 32 + cg];
            if ((wrd >> bit) & 1u) {
                unsigned long long k2 = s_keys[n];
                if (!has || k2 > best) { best = k2; has = true; }
            }
        }
        if (has) {
            code = __uint_as_float((unsigned)(best >> 10));
            fidx = (float)((N_NODES - 1) - (int)(best & 1023ull));
        }
    }

    out_code[p * N_CMP + t] = code;
    out_idx [p * N_CMP + t] = fidx;
}

// ---------------------------------------------------------------------------
extern "C" void kernel_launch(void* const* d_in, const int* in_sizes, int n_in,
                              void* d_out, int out_size) {
    const float* x     = (const float*)d_in[0];
    const int*   edges = (const int*)  d_in[1];
    float*       out   = (float*)d_out;

    pack_transpose_kernel<<<(N_CMP / 32) * (N_NODES / 32), 1024>>>(edges);
    topk_probe_kernel<<<N_PTS, 1024>>>(x, out, out + (size_t)N_PTS * N_CMP);
}

// round 3
// speedup vs baseline: 1.6452x; 1.0078x over previous
#include <cuda_runtime.h>

// Shapes fixed by the dataset:
//   x:                   [N_PTS,  N_NODES] float32
//   learned_edge_states: [N_CMP,  N_NODES] int32 (0 == EDG_NULL)
// Output: concat( new_comp_code [N_PTS,N_CMP] f32, premerge_idx [N_PTS,N_CMP] f32 )
#define N_PTS   256
#define N_NODES 1024
#define N_CMP   1024

// Transposed mask bits: d_maskT[n*32 + cg] bit b == (edges[cg*32+b][n] != 0).
// 128 KB static scratch — L2-resident.
__device__ unsigned d_maskT[N_NODES * (N_CMP / 32)];

// ---------------------------------------------------------------------------
// Kernel 1: pack + transpose, fully warp-local (no smem, no block barriers).
// One warp per 32(comps) x 32(nodes) tile. 32 coalesced 128B loads ->
// ballot-pack over nodes -> ballot-transpose to bits over comps.
// ---------------------------------------------------------------------------
__global__ __launch_bounds__(256)
void pack_transpose_kernel(const int* __restrict__ edges) {
    const unsigned warp = (blockIdx.x * blockDim.x + threadIdx.x) >> 5;
    const unsigned lane = threadIdx.x & 31;
    const unsigned cg   = warp & 31;   // component group
    const unsigned nch  = warp >> 5;   // node chunk

    // bits over nodes, for comp row (cg*32 + r); lane r keeps iteration r.
    unsigned bnodes = 0;
    #pragma unroll
    for (int r = 0; r < 32; ++r) {
        int v = edges[(cg * 32 + r) * N_NODES + nch * 32 + lane];
        unsigned bal = __ballot_sync(0xFFFFFFFFu, v != 0);
        if (lane == (unsigned)r) bnodes = bal;
    }
    // transpose: lane j gets bits over comps for node (nch*32 + j)
    unsigned T = 0;
    #pragma unroll
    for (int j = 0; j < 32; ++j) {
        unsigned bal = __ballot_sync(0xFFFFFFFFu, (bnodes >> j) & 1u);
        if (lane == (unsigned)j) T = bal;
    }
    d_maskT[(nch * 32 + lane) * 32 + cg] = T;
}

// ---------------------------------------------------------------------------
// Kernel 2: per-point exact top-32 selection + batched probe.
// Key: (bits(|x|) << 10) | (1023 - n) -> max key == max value, min index.
// ---------------------------------------------------------------------------
__global__ __launch_bounds__(1024)
void topk_probe_kernel(const float* __restrict__ x,
                       float* __restrict__ out_code,
                       float* __restrict__ out_idx) {
    __shared__ unsigned long long s_a[N_NODES];   // merge ping (8 KB)
    __shared__ unsigned long long s_b[N_NODES];   // merge pong (8 KB)

    const int p    = blockIdx.x;
    const int t    = threadIdx.x;
    const int w    = t >> 5;
    const int lane = t & 31;

    // ---- build key ----
    float xv = __ldg(&x[p * N_NODES + t]);
    unsigned vb = __float_as_uint(fabsf(xv));
    unsigned long long key =
        (((unsigned long long)vb) << 10) | (unsigned)((N_NODES - 1) - t);

    // ---- warp-register bitonic sort (ascending), no barriers ----
    #pragma unroll
    for (int k = 2; k <= 32; k <<= 1) {
        #pragma unroll
        for (int j = k >> 1; j > 0; j >>= 1) {
            unsigned long long other = __shfl_xor_sync(0xFFFFFFFFu, key, j);
            bool dirUp = ((lane & k) == 0);
            bool lower = ((lane & j) == 0);
            unsigned long long mn = key < other ? key : other;
            unsigned long long mx = key < other ? other : key;
            key = (dirUp == lower) ? mn : mx;
        }
    }
    s_a[w * 32 + (31 - lane)] = key;      // store run descending
    __syncthreads();

    // ---- 5 rounds of bitonic top-32 merge: 32 runs -> 1 ----
    unsigned long long* bin  = s_a;
    unsigned long long* bout = s_b;
    #pragma unroll
    for (int r = 0; r < 5; ++r) {
        int nm = 16 >> r;
        if (w < nm) {
            unsigned long long a = bin[(2 * w) * 32 + lane];
            unsigned long long b = bin[(2 * w + 1) * 32 + (31 - lane)];
            unsigned long long m = a > b ? a : b;       // bitonic, holds top-32
            #pragma unroll
            for (int j = 16; j > 0; j >>= 1) {          // merge, descending
                unsigned long long other = __shfl_xor_sync(0xFFFFFFFFu, m, j);
                bool lower = ((lane & j) == 0);
                unsigned long long mn = m < other ? m : other;
                unsigned long long mx = m < other ? other : m;
                m = lower ? mx : mn;
            }
            bout[w * 32 + lane] = m;
        }
        __syncthreads();
        unsigned long long* tmp = bin; bin = bout; bout = tmp;
    }
    const unsigned long long* s_top = bin;   // top-32, descending

    // ---- batched probe: lane kk loads mask word for top-node kk (MLP=32),
    //      then a 32x32 ballot-transpose gives each thread its hit mask. ----
    unsigned long long mykey = s_top[lane];
    int myn = (N_NODES - 1) - (int)(mykey & 1023ull);
    unsigned wrd = __ldg(&d_maskT[(unsigned)myn * 32 + (unsigned)w]);

    unsigned hits = 0;                        // bit kk: top-kk node is masked
    #pragma unroll
    for (int j = 0; j < 32; ++j) {
        unsigned bal = __ballot_sync(0xFFFFFFFFu, (wrd >> j) & 1u);
        if (lane == j) hits = bal;
    }

    float code = 0.0f, fidx = 0.0f;
    if (hits) {
        int kk = __ffs(hits) - 1;             // smallest rank = largest |x|
        unsigned long long k2 = s_top[kk];
        code = __uint_as_float((unsigned)(k2 >> 10));
        fidx = (float)((N_NODES - 1) - (int)(k2 & 1023ull));
    } else {
        // exact fallback (P ~ (1/3)^32 per cell; also handles empty rows)
        const unsigned cg  = (unsigned)t >> 5;
        const unsigned bit = (unsigned)t & 31;
        unsigned long long best = 0; bool has = false;
        for (int n = 0; n < N_NODES; ++n) {
            unsigned mw = __ldg(&d_maskT[(unsigned)n * 32 + cg]);
            if ((mw >> bit) & 1u) {
                float xn = __ldg(&x[p * N_NODES + n]);
                unsigned long long k2 =
                    (((unsigned long long)__float_as_uint(fabsf(xn))) << 10)
                    | (unsigned)((N_NODES - 1) - n);
                if (!has || k2 > best) { best = k2; has = true; }
            }
        }
        if (has) {
            code = __uint_as_float((unsigned)(best >> 10));
            fidx = (float)((N_NODES - 1) - (int)(best & 1023ull));
        }
    }

    out_code[p * N_CMP + t] = code;
    out_idx [p * N_CMP + t] = fidx;
}

// ---------------------------------------------------------------------------
extern "C" void kernel_launch(void* const* d_in, const int* in_sizes, int n_in,
                              void* d_out, int out_size) {
    const float* x     = (const float*)d_in[0];
    const int*   edges = (const int*)  d_in[1];
    float*       out   = (float*)d_out;

    // 1024 tiles, one warp each: 128 blocks x 256 threads.
    pack_transpose_kernel<<<128, 256>>>(edges);
    topk_probe_kernel<<<N_PTS, 1024>>>(x, out, out + (size_t)N_PTS * N_CMP);
}

// round 5
// speedup vs baseline: 1.8190x; 1.1056x over previous
#include <cuda_runtime.h>

// Shapes fixed by the dataset:
//   x:                   [N_PTS,  N_NODES] float32
//   learned_edge_states: [N_CMP,  N_NODES] int32 (0 == EDG_NULL)
// Output: concat( new_comp_code [N_PTS,N_CMP] f32, premerge_idx [N_PTS,N_CMP] f32 )
#define N_PTS   256
#define N_NODES 1024
#define N_CMP   1024

typedef unsigned long long u64;

// Transposed mask bits: d_maskT[n*32 + cg] bit b == (edges[cg*32+b][n] != 0).
// 128 KB static scratch — L2-resident.
__device__ unsigned d_maskT[N_NODES * (N_CMP / 32)];

// ---------------------------------------------------------------------------
// Kernel 1: pack+transpose with NO ballots. Warp <-> (node-chunk, comp-group,
// byte-quarter). lane = node offset; iterate 8 comp rows, build the byte of
// the transposed word directly. 8 independent coalesced LDGs per warp.
// ---------------------------------------------------------------------------
__global__ __launch_bounds__(256)
void pack_kernel(const int* __restrict__ edges) {
    const unsigned gw   = (blockIdx.x * blockDim.x + threadIdx.x) >> 5;
    const unsigned lane = threadIdx.x & 31;
    const unsigned q    = gw & 3;          // byte quarter (comps q*8..q*8+7)
    const unsigned cg   = (gw >> 2) & 31;  // component group
    const unsigned nch  = gw >> 7;         // node chunk
    const unsigned n    = nch * 32 + lane;

    unsigned B = 0;
    #pragma unroll
    for (int r = 0; r < 8; ++r) {
        int v = edges[(cg * 32 + q * 8 + r) * N_NODES + n];
        if (v) B |= 1u << r;
    }
    ((unsigned char*)d_maskT)[(n * 32 + cg) * 4 + q] = (unsigned char)B;
}

// ---------------------------------------------------------------------------
// Kernel 2: per-point exact top-32 (2 keys/thread, dual sort chains for ILP)
// + smem-broadcast probe.
// Key: (bits(|x|) << 10) | (1023 - n) -> max key == max value, min index.
// ---------------------------------------------------------------------------
__device__ __forceinline__ u64 u64max(u64 a, u64 b) { return a > b ? a : b; }
__device__ __forceinline__ u64 u64min(u64 a, u64 b) { return a < b ? a : b; }

__global__ __launch_bounds__(512)
void topk_probe_kernel(const float* __restrict__ x,
                       float* __restrict__ out_code,
                       float* __restrict__ out_idx) {
    __shared__ u64      s_a[512];        // 16 runs ping      (4 KB)
    __shared__ u64      s_b[256];        // pong              (2 KB)
    __shared__ unsigned s_w[32 * 32];    // rank-words per cg (4 KB)

    const int p    = blockIdx.x;
    const int t    = threadIdx.x;
    const int w    = t >> 5;
    const int lane = t & 31;

    // ---- build two keys ----
    float x1 = __ldg(&x[p * N_NODES + t]);
    float x2 = __ldg(&x[p * N_NODES + t + 512]);
    u64 k1 = (((u64)__float_as_uint(fabsf(x1))) << 10)
             | (unsigned)((N_NODES - 1) - t);
    u64 k2 = (((u64)__float_as_uint(fabsf(x2))) << 10)
             | (unsigned)((N_NODES - 1) - (t + 512));

    // ---- two interleaved warp bitonic sorts (ascending), no barriers ----
    #pragma unroll
    for (int k = 2; k <= 32; k <<= 1) {
        #pragma unroll
        for (int j = k >> 1; j > 0; j >>= 1) {
            bool dirUp = ((lane & k) == 0);
            bool lower = ((lane & j) == 0);
            u64 o1 = __shfl_xor_sync(0xFFFFFFFFu, k1, j);
            u64 o2 = __shfl_xor_sync(0xFFFFFFFFu, k2, j);
            k1 = (dirUp == lower) ? u64min(k1, o1) : u64max(k1, o1);
            k2 = (dirUp == lower) ? u64min(k2, o2) : u64max(k2, o2);
        }
    }

    // ---- in-register merge: top-32 of this warp's 64 elements ----
    // k1 reversed -> descending; max(desc, asc) is bitonic and holds top-32.
    u64 a = __shfl_xor_sync(0xFFFFFFFFu, k1, 31);     // descending
    u64 m = u64max(a, k2);                            // bitonic top-32
    #pragma unroll
    for (int j = 16; j > 0; j >>= 1) {                // merge -> descending
        u64 o = __shfl_xor_sync(0xFFFFFFFFu, m, j);
        bool lower = ((lane & j) == 0);
        m = lower ? u64max(m, o) : u64min(m, o);
    }
    s_a[w * 32 + lane] = m;
    __syncthreads();

    // ---- tree: 16 runs -> 1 (4 rounds: A->B->A->B->A) ----
    u64* bin  = s_a;
    u64* bout = s_b;
    #pragma unroll
    for (int r = 0; r < 4; ++r) {
        int nm = 8 >> r;
        if (w < nm) {
            u64 aa = bin[(2 * w) * 32 + lane];
            u64 bb = bin[(2 * w + 1) * 32 + (31 - lane)];
            u64 mm = u64max(aa, bb);
            #pragma unroll
            for (int j = 16; j > 0; j >>= 1) {
                u64 o = __shfl_xor_sync(0xFFFFFFFFu, mm, j);
                bool lower = ((lane & j) == 0);
                mm = lower ? u64max(mm, o) : u64min(mm, o);
            }
            bout[w * 32 + lane] = mm;
        }
        __syncthreads();
        u64* tmp = bin; bin = bout; bout = tmp;
    }
    // final top-32 run (descending) is in s_a[0..31]
    const u64* s_top = s_a;

    // ---- stage rank-words: lane kk loads mask word for top-node kk, for the
    //      two comp-groups this warp serves (w and w+16). MLP=2 per lane. ----
    {
        u64 keyl = s_top[lane];
        int  nl  = (N_NODES - 1) - (int)(keyl & 1023ull);
        unsigned wa = __ldg(&d_maskT[(unsigned)nl * 32 + (unsigned)w]);
        unsigned wb = __ldg(&d_maskT[(unsigned)nl * 32 + (unsigned)(w + 16)]);
        s_w[w * 32 + lane]        = wa;
        s_w[(w + 16) * 32 + lane] = wb;
    }
    __syncthreads();

    // ---- probe both comps of this thread ----
    #pragma unroll
    for (int half = 0; half < 2; ++half) {
        const int      c   = t + half * 512;
        const unsigned cg  = (unsigned)c >> 5;       // warp-uniform
        const unsigned bit = (unsigned)c & 31;

        float code = 0.0f, fidx = 0.0f;
        bool found = false;
        #pragma unroll 4
        for (int kk = 0; kk < 32; ++kk) {
            unsigned wrd = s_w[cg * 32 + kk];        // broadcast LDS
            if ((wrd >> bit) & 1u) {
                u64 k3 = s_top[kk];
                code = __uint_as_float((unsigned)(k3 >> 10));
                fidx = (float)((N_NODES - 1) - (int)(k3 & 1023ull));
                found = true;
                break;
            }
        }
        if (!found) {
            // exact fallback (P ~ (1/3)^32 per cell; also covers empty rows)
            u64 best = 0; bool has = false;
            for (int n = 0; n < N_NODES; ++n) {
                unsigned mw = __ldg(&d_maskT[(unsigned)n * 32 + cg]);
                if ((mw >> bit) & 1u) {
                    float xn = __ldg(&x[p * N_NODES + n]);
                    u64 k3 = (((u64)__float_as_uint(fabsf(xn))) << 10)
                             | (unsigned)((N_NODES - 1) - n);
                    if (!has || k3 > best) { best = k3; has = true; }
                }
            }
            if (has) {
                code = __uint_as_float((unsigned)(best >> 10));
                fidx = (float)((N_NODES - 1) - (int)(best & 1023ull));
            }
        }
        out_code[p * N_CMP + c] = code;
        out_idx [p * N_CMP + c] = fidx;
    }
}

// ---------------------------------------------------------------------------
extern "C" void kernel_launch(void* const* d_in, const int* in_sizes, int n_in,
                              void* d_out, int out_size) {
    const float* x     = (const float*)d_in[0];
    const int*   edges = (const int*)  d_in[1];
    float*       out   = (float*)d_out;

    // 4096 warps: 512 blocks x 256 threads (32 nch * 32 cg * 4 quarters)
    pack_kernel<<<512, 256>>>(edges);
    topk_probe_kernel<<<N_PTS, 512>>>(x, out, out + (size_t)N_PTS * N_CMP);
}

// round 6
// speedup vs baseline: 2.1047x; 1.1571x over previous
#include <cuda_runtime.h>

// Shapes fixed by the dataset:
//   x:                   [N_PTS,  N_NODES] float32
//   learned_edge_states: [N_CMP,  N_NODES] int32 (0 == EDG_NULL)
// Output: concat( new_comp_code [N_PTS,N_CMP] f32, premerge_idx [N_PTS,N_CMP] f32 )
#define N_PTS   256
#define N_NODES 1024
#define N_CMP   1024

#define THR  2.2f     // |x| filter threshold: E[count]=28.5, sd=5.2 for N(0,1)
#define CAP  64       // candidate buffer capacity (P(count>64) ~ 1e-11)

typedef unsigned long long u64;

// Transposed mask bits: d_maskT[n*32 + cg] bit b == (edges[cg*32+b][n] != 0).
// 128 KB static scratch — L2-resident.
__device__ unsigned d_maskT[N_NODES * (N_CMP / 32)];

// ---------------------------------------------------------------------------
// Kernel 1: pack+transpose, no ballots. Warp <-> (node-chunk, comp-group,
// byte-quarter); lane = node offset; 8 coalesced LDGs build one byte.
// ---------------------------------------------------------------------------
__global__ __launch_bounds__(256)
void pack_kernel(const int* __restrict__ edges) {
    const unsigned gw   = (blockIdx.x * blockDim.x + threadIdx.x) >> 5;
    const unsigned lane = threadIdx.x & 31;
    const unsigned q    = gw & 3;          // byte quarter (comps q*8..q*8+7)
    const unsigned cg   = (gw >> 2) & 31;  // component group
    const unsigned nch  = gw >> 7;         // node chunk
    const unsigned n    = nch * 32 + lane;

    unsigned B = 0;
    #pragma unroll
    for (int r = 0; r < 8; ++r) {
        int v = edges[(cg * 32 + q * 8 + r) * N_NODES + n];
        if (v) B |= 1u << r;
    }
    ((unsigned char*)d_maskT)[(n * 32 + cg) * 4 + q] = (unsigned char)B;
}

// ---------------------------------------------------------------------------
// Kernel 2: threshold-filter -> single-warp sort of candidates -> probe.
// Key: (bits(|x|) << 10) | (1023 - n) -> max key == max value, min index.
// ---------------------------------------------------------------------------
__device__ __forceinline__ u64 u64max(u64 a, u64 b) { return a > b ? a : b; }
__device__ __forceinline__ u64 u64min(u64 a, u64 b) { return a < b ? a : b; }

// Exact per-component scan (rare path; also used on overflow / empty comps).
__device__ __forceinline__ void exact_scan(const float* __restrict__ x,
                                           int p, unsigned cg, unsigned bit,
                                           float& code, float& fidx) {
    u64 best = 0; bool has = false;
    for (int n = 0; n < N_NODES; ++n) {
        unsigned mw = __ldg(&d_maskT[(unsigned)n * 32 + cg]);
        if ((mw >> bit) & 1u) {
            float xn = __ldg(&x[p * N_NODES + n]);
            u64 k = (((u64)__float_as_uint(fabsf(xn))) << 10)
                    | (unsigned)((N_NODES - 1) - n);
            if (!has || k > best) { best = k; has = true; }
        }
    }
    if (has) {
        code = __uint_as_float((unsigned)(best >> 10));
        fidx = (float)((N_NODES - 1) - (int)(best & 1023ull));
    } else {
        code = 0.0f; fidx = 0.0f;
    }
}

__global__ __launch_bounds__(512)
void filter_probe_kernel(const float* __restrict__ x,
                         float* __restrict__ out_code,
                         float* __restrict__ out_idx) {
    __shared__ u64      s_cand[CAP];
    __shared__ u64      s_top[32];
    __shared__ unsigned s_w[32 * 32];     // rank-words per comp-group (4 KB)
    __shared__ int      s_cnt;

    const int p    = blockIdx.x;
    const int t    = threadIdx.x;
    const int w    = t >> 5;
    const int lane = t & 31;

    if (t == 0) s_cnt = 0;
    __syncthreads();

    // ---- filter: each thread inspects 2 consecutive elements (float2) ----
    float2 xv = __ldg(&((const float2*)(x + p * N_NODES))[t]);
    #pragma unroll
    for (int e = 0; e < 2; ++e) {
        float    av   = fabsf(e == 0 ? xv.x : xv.y);
        int      n    = 2 * t + e;
        bool     pred = (av > THR);
        unsigned bal  = __ballot_sync(0xFFFFFFFFu, pred);
        int base = 0;
        if (lane == 0 && bal) base = atomicAdd(&s_cnt, __popc(bal));
        base = __shfl_sync(0xFFFFFFFFu, base, 0);
        if (pred) {
            int pos = base + __popc(bal & ((1u << lane) - 1u));
            if (pos < CAP) {
                s_cand[pos] = (((u64)__float_as_uint(av)) << 10)
                              | (unsigned)((N_NODES - 1) - n);
            }
        }
    }
    __syncthreads();

    const int  cnt = s_cnt;
    const bool ovf = (cnt > CAP);          // block-uniform; P ~ 1e-11

    if (!ovf) {
        // ---- warp 0: dual bitonic sort + merge -> top-32 descending ----
        if (w == 0) {
            u64 k1 = (lane      < cnt) ? s_cand[lane]      : 0ull;
            u64 k2 = (lane + 32 < cnt) ? s_cand[lane + 32] : 0ull;
            #pragma unroll
            for (int k = 2; k <= 32; k <<= 1) {
                #pragma unroll
                for (int j = k >> 1; j > 0; j >>= 1) {
                    bool dirUp = ((lane & k) == 0);
                    bool lower = ((lane & j) == 0);
                    u64 o1 = __shfl_xor_sync(0xFFFFFFFFu, k1, j);
                    u64 o2 = __shfl_xor_sync(0xFFFFFFFFu, k2, j);
                    k1 = (dirUp == lower) ? u64min(k1, o1) : u64max(k1, o1);
                    k2 = (dirUp == lower) ? u64min(k2, o2) : u64max(k2, o2);
                }
            }
            u64 a = __shfl_xor_sync(0xFFFFFFFFu, k1, 31);   // descending
            u64 m = u64max(a, k2);                          // bitonic top-32
            #pragma unroll
            for (int j = 16; j > 0; j >>= 1) {              // -> descending
                u64 o = __shfl_xor_sync(0xFFFFFFFFu, m, j);
                bool lower = ((lane & j) == 0);
                m = lower ? u64max(m, o) : u64min(m, o);
            }
            s_top[lane] = m;
        }
        __syncthreads();

        const int n_valid = cnt < 32 ? cnt : 32;

        // ---- stage rank-words: lane kk loads mask word for top-kk node,
        //      warp w serves comp-groups w and w+16 ----
        {
            u64 keyl = s_top[lane];
            int  nl  = (N_NODES - 1) - (int)(keyl & 1023ull);
            s_w[w * 32 + lane]        = __ldg(&d_maskT[(unsigned)nl * 32 + (unsigned)w]);
            s_w[(w + 16) * 32 + lane] = __ldg(&d_maskT[(unsigned)nl * 32 + (unsigned)(w + 16)]);
        }
        __syncthreads();

        // ---- probe both comps of this thread ----
        #pragma unroll
        for (int half = 0; half < 2; ++half) {
            const int      c   = t + half * 512;
            const unsigned cg  = (unsigned)c >> 5;       // warp-uniform
            const unsigned bit = (unsigned)c & 31;

            float code, fidx;
            bool found = false;
            for (int kk = 0; kk < n_valid; ++kk) {
                unsigned wrd = s_w[cg * 32 + kk];        // broadcast LDS
                if ((wrd >> bit) & 1u) {
                    u64 k3 = s_top[kk];
                    code = __uint_as_float((unsigned)(k3 >> 10));
                    fidx = (float)((N_NODES - 1) - (int)(k3 & 1023ull));
                    found = true;
                    break;
                }
            }
            if (!found) {
                // comp's masked max below THR (P~1e-9/comp) or empty comp
                exact_scan(x, p, cg, bit, code, fidx);
            }
            out_code[p * N_CMP + c] = code;
            out_idx [p * N_CMP + c] = fidx;
        }
    } else {
        // overflow: exact path for every comp this thread owns
        #pragma unroll
        for (int half = 0; half < 2; ++half) {
            const int      c   = t + half * 512;
            const unsigned cg  = (unsigned)c >> 5;
            const unsigned bit = (unsigned)c & 31;
            float code, fidx;
            exact_scan(x, p, cg, bit, code, fidx);
            out_code[p * N_CMP + c] = code;
            out_idx [p * N_CMP + c] = fidx;
        }
    }
}

// ---------------------------------------------------------------------------
extern "C" void kernel_launch(void* const* d_in, const int* in_sizes, int n_in,
                              void* d_out, int out_size) {
    const float* x     = (const float*)d_in[0];
    const int*   edges = (const int*)  d_in[1];
    float*       out   = (float*)d_out;

    // 4096 warps: 512 blocks x 256 threads (32 nch * 32 cg * 4 quarters)
    pack_kernel<<<512, 256>>>(edges);
    filter_probe_kernel<<<N_PTS, 512>>>(x, out, out + (size_t)N_PTS * N_CMP);
}